// round 7
// baseline (speedup 1.0000x reference)
#include <cuda_runtime.h>

// SSIM loss over [8,8,3,256,256] fp32 -> scalar.
// Streaming-accumulator vertical 11-tap Gaussian (ring of 11 pending outputs,
// FFMA-imm), swizzled smem row-chunk buffer for horizontal pass, fused SSIM +
// last-block-done final reduction. 2 CTAs/SM.

#define NPLANES 192
#define HW      256
#define TSY     32
#define CH      8
#define NCH     4
#define FST     272
#define NSTRIP  8
#define NBLOCKS (NPLANES * NSTRIP)   // 1536

__device__ float g_partial[NBLOCKS];
__device__ unsigned int g_cnt = 0;

// Gaussian ws=11 sigma=1.5 normalized
#define G0 0.00102838f
#define G1 0.00759876f
#define G2 0.03600077f
#define G3 0.10936070f
#define G4 0.21300548f
#define G5 0.26601173f

#define SWZ(b) ((b) ^ (((b) >> 3) & 0x70))

__device__ __forceinline__ float ssim_px(float mx, float my, float mxx,
                                         float myy, float mxy) {
    float mx2 = mx * mx;
    float my2 = my * my;
    float mab = mx * my;
    float sx2 = fmaxf(mxx - mx2, 0.f);
    float sy2 = fmaxf(myy - my2, 0.f);
    float sxy = mxy - mab;
    float num = fmaf(2.f, mab, 1e-4f) * fmaf(2.f, sxy, 9e-4f);
    float den = (mx2 + my2 + 1e-4f) * (sx2 + sy2 + 9e-4f) + 1e-8f;
    return __fdividef(num, den);
}

// Input row RR (strip-relative, may be negative) contributes to pending
// outputs o in [RR-5, RR+5] clipped to [0,31]. First tap (kk==0) overwrites
// the ring slot, so no zero-init or reset is ever needed.
#define VROW(RR, X, Y) do {                                                   \
    float _xx = (X) * (X), _yy = (Y) * (Y), _xy = (X) * (Y);                  \
    _Pragma("unroll")                                                         \
    for (int o = ((RR) >= 5 ? (RR) - 5 : 0);                                  \
         o <= ((RR) + 5 <= 31 ? (RR) + 5 : 31); o++) {                        \
        const int kk = (RR) - o + 5;                                          \
        const int s = o % 11;                                                 \
        if (kk == 0) {                                                        \
            ax[s]  = G[0] * (X);  ay[s]  = G[0] * (Y);                        \
            axx[s] = G[0] * _xx;  ayy[s] = G[0] * _yy;  axy[s] = G[0] * _xy;  \
        } else {                                                              \
            ax[s]  = fmaf(G[kk], (X), ax[s]);                                 \
            ay[s]  = fmaf(G[kk], (Y), ay[s]);                                 \
            axx[s] = fmaf(G[kk], _xx, axx[s]);                                \
            ayy[s] = fmaf(G[kk], _yy, ayy[s]);                                \
            axy[s] = fmaf(G[kk], _xy, axy[s]);                                \
        }                                                                     \
    }                                                                         \
} while (0)

#define RETIRE(OO) do {                                                       \
    const int _s = (OO) % 11;                                                 \
    const int _fr = (OO) % 8;                                                 \
    int _b;                                                                   \
    _b = ((0 * CH + _fr) * FST + 8 + t) * 4;                                  \
    *(float*)((char*)fbuf + SWZ(_b)) = ax[_s];                                \
    _b = ((1 * CH + _fr) * FST + 8 + t) * 4;                                  \
    *(float*)((char*)fbuf + SWZ(_b)) = ay[_s];                                \
    _b = ((2 * CH + _fr) * FST + 8 + t) * 4;                                  \
    *(float*)((char*)fbuf + SWZ(_b)) = axx[_s];                               \
    _b = ((3 * CH + _fr) * FST + 8 + t) * 4;                                  \
    *(float*)((char*)fbuf + SWZ(_b)) = ayy[_s];                               \
    _b = ((4 * CH + _fr) * FST + 8 + t) * 4;                                  \
    *(float*)((char*)fbuf + SWZ(_b)) = axy[_s];                               \
} while (0)

__global__ __launch_bounds__(256, 2) void ssim_main_kernel(
    const float* __restrict__ pred, const float* __restrict__ tgt,
    float* __restrict__ out)
{
    __shared__ __align__(128) float fbuf[5 * CH * FST];   // 43,520 B
    __shared__ float wsum[8];
    __shared__ double dsum[8];
    __shared__ int lastflag;

    const float G[11] = {G0, G1, G2, G3, G4, G5, G4, G3, G2, G1, G0};

    const int t = threadIdx.x;             // image column
    const int strip = blockIdx.x;
    const int p = blockIdx.y;
    const float* __restrict__ px = pred + (size_t)p * HW * HW;
    const float* __restrict__ py = tgt  + (size_t)p * HW * HW;
    const int gy0 = strip * TSY;

    // Zero whole field buffer (covers zero-pad columns); barrier before use.
    for (int i = t; i < 5 * CH * FST; i += 256) fbuf[i] = 0.f;
    __syncthreads();

    float ax[11], ay[11], axx[11], ayy[11], axy[11];

    // Prologue: rows gy0-5 .. gy0+4
#pragma unroll
    for (int j = 0; j < 10; j++) {
        const int RR = j - 5;
        int r = gy0 + RR;
        float x = 0.f, y = 0.f;
        if ((unsigned)r < HW) {
            x = __saturatef(px[r * HW + t]);
            y = __saturatef(py[r * HW + t]);
        }
        VROW(RR, x, y);
    }

    // Prefetch chunk 0 rows gy0+5 .. gy0+12
    float pfx[8], pfy[8];
#pragma unroll
    for (int j = 0; j < 8; j++) {
        int r = gy0 + 5 + j;
        pfx[j] = (r < HW) ? px[r * HW + t] : 0.f;
        pfy[j] = (r < HW) ? py[r * HW + t] : 0.f;
    }

    const int hrow = t >> 5;
    const int lane = t & 31;
    float lsum = 0.f;

#pragma unroll
    for (int cc = 0; cc < NCH; cc++) {
        if (cc > 0) __syncthreads();       // previous chunk's H-pass done
        // V-pass: rows 5+8cc .. 12+8cc, retiring outputs 8cc .. 8cc+7
#pragma unroll
        for (int j = 0; j < 8; j++) {
            const int RR = 5 + 8 * cc + j;
            float x = __saturatef(pfx[j]);
            float y = __saturatef(pfy[j]);
            VROW(RR, x, y);
            RETIRE(RR - 5);
        }
        // Prefetch next chunk's rows (latency hidden by H-pass)
        if (cc < NCH - 1) {
#pragma unroll
            for (int j = 0; j < 8; j++) {
                int r = gy0 + 13 + 8 * cc + j;
                pfx[j] = (r < HW) ? px[r * HW + t] : 0.f;
                pfy[j] = (r < HW) ? py[r * HW + t] : 0.f;
            }
        }
        __syncthreads();                   // fbuf chunk ready

        // H-pass + SSIM: 2 groups of 4 px per thread
#pragma unroll
        for (int gq = 0; gq < 2; gq++) {
            const int cg = lane * 8 + gq * 4;    // first output image col
            float hv[5][4];
#pragma unroll
            for (int f = 0; f < 5; f++) {
                float v[20];                     // padded cols cg .. cg+19
#pragma unroll
                for (int m = 0; m < 5; m++) {
                    int b = ((f * CH + hrow) * FST + cg + 4 * m) * 4;
                    float4 q4 = *(const float4*)((const char*)fbuf + SWZ(b));
                    v[4 * m + 0] = q4.x; v[4 * m + 1] = q4.y;
                    v[4 * m + 2] = q4.z; v[4 * m + 3] = q4.w;
                }
#pragma unroll
                for (int q = 0; q < 4; q++) {
                    float a = G[0] * v[q + 3];
#pragma unroll
                    for (int k = 1; k < 11; k++)
                        a = fmaf(G[k], v[q + 3 + k], a);
                    hv[f][q] = a;
                }
            }
#pragma unroll
            for (int q = 0; q < 4; q++)
                lsum += ssim_px(hv[0][q], hv[1][q], hv[2][q], hv[3][q], hv[4][q]);
        }
    }

    // Block reduction -> partial
#pragma unroll
    for (int off = 16; off; off >>= 1)
        lsum += __shfl_xor_sync(0xFFFFFFFFu, lsum, off);
    if (lane == 0) wsum[t >> 5] = lsum;
    __syncthreads();
    if (t == 0) {
        float s = 0.f;
#pragma unroll
        for (int w = 0; w < 8; w++) s += wsum[w];
        g_partial[p * NSTRIP + strip] = s;
        __threadfence();
        unsigned int n = atomicAdd(&g_cnt, 1u);
        lastflag = (n == NBLOCKS - 1);
    }
    __syncthreads();

    // Last block: deterministic final reduction over all partials
    if (lastflag) {
        double s = 0.0;
        for (int i = t; i < NBLOCKS; i += 256)
            s += (double)__ldcg(&g_partial[i]);
#pragma unroll
        for (int off = 16; off; off >>= 1)
            s += __shfl_xor_sync(0xFFFFFFFFu, s, off);
        if (lane == 0) dsum[t >> 5] = s;
        __syncthreads();
        if (t == 0) {
            double v = 0.0;
#pragma unroll
            for (int w = 0; w < 8; w++) v += dsum[w];
            out[0] = 1.0f - (float)(v / (double)(NPLANES * HW * HW));
            g_cnt = 0;                     // reset for next replay
        }
    }
}

extern "C" void kernel_launch(void* const* d_in, const int* in_sizes, int n_in,
                              void* d_out, int out_size)
{
    const float* pred = (const float*)d_in[0];
    const float* tgt  = (const float*)d_in[1];
    float* out = (float*)d_out;

    dim3 grid(NSTRIP, NPLANES);
    ssim_main_kernel<<<grid, 256>>>(pred, tgt, out);
}